// round 2
// baseline (speedup 1.0000x reference)
#include <cuda_runtime.h>
#include <stdint.h>

// Problem constants (shapes are fixed by the dataset)
#define NN      100000
#define FDIM    128
#define HDIM    256
#define EMAX    1800000
#define NEG_SLOPE 0.2f

// -------- scratch (static device allocations; no runtime malloc) ----------
__device__ float    g_h   [(size_t)NN * FDIM];   // h = x @ W
__device__ float    g_asrc[NN];
__device__ float    g_adst[NN];
__device__ float    g_gat [(size_t)NN * FDIM];   // GAT output accumulator
__device__ float    g_h1  [(size_t)NN * HDIM];
__device__ float    g_h2  [(size_t)NN * HDIM];
__device__ float    g_e   [EMAX];                // edge logits, then p
__device__ unsigned g_mkey[NN];                  // segment max (monotone-key encoded)
__device__ float    g_z   [NN];                  // segment sum
__device__ int      g_src [EMAX];                // compact edge endpoints (incl. self loops)
__device__ int      g_dst [EMAX];
__device__ int      g_is64;                      // 1 if edge buffer is int64-layout

// order-preserving float -> unsigned key (for atomicMax on floats)
__device__ __forceinline__ unsigned f2key(float f) {
    unsigned b = __float_as_uint(f);
    return (b & 0x80000000u) ? ~b : (b | 0x80000000u);
}
__device__ __forceinline__ float key2f(unsigned k) {
    unsigned b = (k & 0x80000000u) ? (k ^ 0x80000000u) : ~k;
    return __uint_as_float(b);
}

// --------------------------- dtype probe ---------------------------
// If the buffer holds int64 values < 2^31, every odd 32-bit word is 0.
// If it holds int32 random node ids, 4096 consecutive odd words being all
// zero has probability ~0.  Single block, deterministic.
__global__ void k_detect(const int* __restrict__ ei, int E) {
    __shared__ int nz;
    if (threadIdx.x == 0) nz = 0;
    __syncthreads();
    int samples = 4096;
    if (samples > E) samples = E;
    for (int i = threadIdx.x; i < samples; i += blockDim.x)
        if (ei[2 * i + 1] != 0) atomicOr(&nz, 1);
    __syncthreads();
    if (threadIdx.x == 0) g_is64 = (nz == 0) ? 1 : 0;
}

// --------------------------- edge expansion (+ self loops) ---------------
__global__ void k_convert(const int* __restrict__ ei, int E, int n) {
    int tot = E + n;
    int stride = gridDim.x * blockDim.x;
    int is64 = g_is64;
    for (int idx = blockIdx.x * blockDim.x + threadIdx.x; idx < tot; idx += stride) {
        int s, d;
        if (idx < E) {
            if (is64) { s = ei[2 * idx]; d = ei[2 * E + 2 * idx]; }
            else      { s = ei[idx];     d = ei[E + idx]; }
        } else {
            s = d = idx - E;
        }
        g_src[idx] = s;
        g_dst[idx] = d;
    }
}

// --------------------------- init ---------------------------
__global__ void k_init(int n) {
    int stride = gridDim.x * blockDim.x;
    int tid = blockIdx.x * blockDim.x + threadIdx.x;
    int total = n * FDIM;
    for (int i = tid; i < total; i += stride) g_gat[i] = 0.f;
    for (int i = tid; i < n; i += stride) { g_z[i] = 0.f; g_mkey[i] = 0u; }
}

// --------------------------- sgemm (fp32, 128x128x16, 8x8 per thread) -----
template<bool RELU, bool ABIAS, bool CBIAS>
__global__ void __launch_bounds__(256) k_sgemm(
    const float* __restrict__ A, const float* __restrict__ B,
    float* __restrict__ C,
    const float* __restrict__ abias,   // added to A elements along K
    const float* __restrict__ cbias,   // added to C along N
    int M, int N, int K)
{
    constexpr int BM = 128, BN = 128, BK = 16;
    __shared__ float As[BK][BM];
    __shared__ float Bs[BK][BN];

    const int tid = threadIdx.x;
    const int tr = tid >> 4;      // 0..15  -> rows tr*8..tr*8+7
    const int tc = tid & 15;      // 0..15  -> cols tc*8..tc*8+7
    const int rowBase = blockIdx.y * BM;
    const int colBase = blockIdx.x * BN;

    float acc[8][8];
#pragma unroll
    for (int i = 0; i < 8; i++)
#pragma unroll
        for (int j = 0; j < 8; j++) acc[i][j] = 0.f;

    for (int k0 = 0; k0 < K; k0 += BK) {
        // ---- load A tile (BM x BK), store transposed As[k][m]
#pragma unroll
        for (int it = 0; it < 2; it++) {
            int idx = tid + it * 256;      // 0..511 float4 slots
            int r = idx >> 2;              // 0..127 row in tile
            int c4 = idx & 3;              // 0..3   float4 within the 16-wide K slab
            int gr = rowBase + r;
            float4 v = make_float4(0.f, 0.f, 0.f, 0.f);
            if (gr < M) {
                v = *(const float4*)(A + (size_t)gr * K + k0 + c4 * 4);
                if (ABIAS) {
                    float4 bb = *(const float4*)(abias + k0 + c4 * 4);
                    v.x += bb.x; v.y += bb.y; v.z += bb.z; v.w += bb.w;
                }
            }
            As[c4 * 4 + 0][r] = v.x;
            As[c4 * 4 + 1][r] = v.y;
            As[c4 * 4 + 2][r] = v.z;
            As[c4 * 4 + 3][r] = v.w;
        }
        // ---- load B tile (BK x BN)
#pragma unroll
        for (int it = 0; it < 2; it++) {
            int idx = tid + it * 256;
            int r = idx >> 5;              // 0..15
            int c = (idx & 31) * 4;        // 0..124
            *(float4*)&Bs[r][c] =
                *(const float4*)(B + (size_t)(k0 + r) * N + colBase + c);
        }
        __syncthreads();

#pragma unroll
        for (int kk = 0; kk < BK; kk++) {
            float a[8], b[8];
            *(float4*)&a[0] = *(float4*)&As[kk][tr * 8];
            *(float4*)&a[4] = *(float4*)&As[kk][tr * 8 + 4];
            *(float4*)&b[0] = *(float4*)&Bs[kk][tc * 8];
            *(float4*)&b[4] = *(float4*)&Bs[kk][tc * 8 + 4];
#pragma unroll
            for (int i = 0; i < 8; i++)
#pragma unroll
                for (int j = 0; j < 8; j++)
                    acc[i][j] += a[i] * b[j];
        }
        __syncthreads();
    }

    // ---- epilogue
#pragma unroll
    for (int i = 0; i < 8; i++) {
        int gr = rowBase + tr * 8 + i;
        if (gr >= M) continue;
#pragma unroll
        for (int j4 = 0; j4 < 2; j4++) {
            int gc = colBase + tc * 8 + j4 * 4;
            float4 v;
            v.x = acc[i][j4 * 4 + 0];
            v.y = acc[i][j4 * 4 + 1];
            v.z = acc[i][j4 * 4 + 2];
            v.w = acc[i][j4 * 4 + 3];
            if (CBIAS) {
                float4 bb = *(const float4*)(cbias + gc);
                v.x += bb.x; v.y += bb.y; v.z += bb.z; v.w += bb.w;
            }
            if (RELU) {
                v.x = fmaxf(v.x, 0.f); v.y = fmaxf(v.y, 0.f);
                v.z = fmaxf(v.z, 0.f); v.w = fmaxf(v.w, 0.f);
            }
            *(float4*)(C + (size_t)gr * N + gc) = v;
        }
    }
}

// --------------------------- per-node attention dots ----------------------
__global__ void k_att(const float* __restrict__ att_src,
                      const float* __restrict__ att_dst, int n) {
    int w = (blockIdx.x * blockDim.x + threadIdx.x) >> 5;
    int lane = threadIdx.x & 31;
    if (w >= n) return;
    float4 hv = ((const float4*)(g_h + (size_t)w * FDIM))[lane];
    float4 as = ((const float4*)att_src)[lane];
    float4 ad = ((const float4*)att_dst)[lane];
    float s = hv.x * as.x + hv.y * as.y + hv.z * as.z + hv.w * as.w;
    float d = hv.x * ad.x + hv.y * ad.y + hv.z * ad.z + hv.w * ad.w;
#pragma unroll
    for (int o = 16; o; o >>= 1) {
        s += __shfl_xor_sync(0xFFFFFFFFu, s, o);
        d += __shfl_xor_sync(0xFFFFFFFFu, d, o);
    }
    if (lane == 0) { g_asrc[w] = s; g_adst[w] = d; }
}

// --------------------------- edge pass 1: logits + segment max ------------
__global__ void k_edge_max(int tot) {
    int stride = gridDim.x * blockDim.x;
    for (int idx = blockIdx.x * blockDim.x + threadIdx.x; idx < tot; idx += stride) {
        int src = g_src[idx], dst = g_dst[idx];
        float e = g_asrc[src] + g_adst[dst];
        e = (e > 0.f) ? e : NEG_SLOPE * e;
        g_e[idx] = e;
        atomicMax(&g_mkey[dst], f2key(e));
    }
}

// --------------------------- edge pass 2: exp + segment sum ---------------
__global__ void k_edge_exp(int tot) {
    int stride = gridDim.x * blockDim.x;
    for (int idx = blockIdx.x * blockDim.x + threadIdx.x; idx < tot; idx += stride) {
        int dst = g_dst[idx];
        float m = key2f(g_mkey[dst]);
        float p = expf(g_e[idx] - m);
        g_e[idx] = p;
        atomicAdd(&g_z[dst], p);
    }
}

// --------------------------- edge pass 3: weighted scatter ----------------
// one warp per edge: 32 lanes x float4 = 128 features
__global__ void k_scatter(int tot) {
    int w = (blockIdx.x * blockDim.x + threadIdx.x) >> 5;
    int lane = threadIdx.x & 31;
    if (w >= tot) return;
    int src = g_src[w], dst = g_dst[w];
    float alpha = g_e[w] / g_z[dst];
    float4 v = ((const float4*)(g_h + (size_t)src * FDIM))[lane];
    float* out = g_gat + (size_t)dst * FDIM + lane * 4;
    atomicAdd(out + 0, alpha * v.x);
    atomicAdd(out + 1, alpha * v.y);
    atomicAdd(out + 2, alpha * v.z);
    atomicAdd(out + 3, alpha * v.w);
}

// --------------------------- final 256->1 + sigmoid -----------------------
__global__ void k_final(const float* __restrict__ W3,
                        const float* __restrict__ b3,
                        float* __restrict__ out, int n) {
    int w = (blockIdx.x * blockDim.x + threadIdx.x) >> 5;
    int lane = threadIdx.x & 31;
    if (w >= n) return;
    const float4* hp = (const float4*)(g_h2 + (size_t)w * HDIM);
    const float4* wp = (const float4*)W3;
    float acc = 0.f;
#pragma unroll
    for (int j = 0; j < 2; j++) {
        float4 h = hp[lane + 32 * j];
        float4 ww = wp[lane + 32 * j];
        acc += h.x * ww.x + h.y * ww.y + h.z * ww.z + h.w * ww.w;
    }
#pragma unroll
    for (int o = 16; o; o >>= 1) acc += __shfl_xor_sync(0xFFFFFFFFu, acc, o);
    if (lane == 0) out[w] = 1.f / (1.f + expf(-(acc + b3[0])));
}

// --------------------------- host launcher --------------------------------
extern "C" void kernel_launch(void* const* d_in, const int* in_sizes, int n_in,
                              void* d_out, int out_size) {
    const float* x       = (const float*)d_in[0];
    const int*   ei      = (const int*)d_in[1];      // int32 OR int64 layout (probed)
    const float* W       = (const float*)d_in[2];
    const float* att_src = (const float*)d_in[3];
    const float* att_dst = (const float*)d_in[4];
    const float* bias    = (const float*)d_in[5];
    const float* W1      = (const float*)d_in[6];
    const float* b1      = (const float*)d_in[7];
    const float* W2      = (const float*)d_in[8];
    const float* b2      = (const float*)d_in[9];
    const float* W3      = (const float*)d_in[10];
    const float* b3      = (const float*)d_in[11];
    float* out = (float*)d_out;

    int n = in_sizes[0] / FDIM;     // 100000 nodes
    int E = in_sizes[1] / 2;        // 1600000 edges (element count / 2 either dtype)
    int Etot = E + n;

    void *p_h, *p_gat, *p_h1, *p_h2;
    cudaGetSymbolAddress(&p_h,   g_h);
    cudaGetSymbolAddress(&p_gat, g_gat);
    cudaGetSymbolAddress(&p_h1,  g_h1);
    cudaGetSymbolAddress(&p_h2,  g_h2);

    int mBlocks = (n + 127) / 128;

    // probe edge dtype, expand edges (+ self loops), init accumulators
    k_detect<<<1, 256>>>(ei, E);
    k_convert<<<2048, 256>>>(ei, E, n);
    k_init<<<1024, 256>>>(n);

    // h = x @ W         [100000,128] = [100000,128] @ [128,128]
    k_sgemm<false, false, false><<<dim3(1, mBlocks), 256>>>(
        x, W, (float*)p_h, nullptr, nullptr, n, FDIM, FDIM);

    // a_src / a_dst
    k_att<<<(n + 7) / 8, 256>>>(att_src, att_dst, n);

    // edge softmax passes
    k_edge_max<<<(Etot + 255) / 256, 256>>>(Etot);
    k_edge_exp<<<(Etot + 255) / 256, 256>>>(Etot);
    k_scatter<<<(Etot + 7) / 8, 256>>>(Etot);

    // MLP layer 1: h1 = relu((gat + bias) @ W1 + b1)   K=128 N=256
    k_sgemm<true, true, true><<<dim3(2, mBlocks), 256>>>(
        (const float*)p_gat, W1, (float*)p_h1, bias, b1, n, HDIM, FDIM);

    // MLP layer 2: h2 = relu(h1 @ W2 + b2)             K=256 N=256
    k_sgemm<true, false, true><<<dim3(2, mBlocks), 256>>>(
        (const float*)p_h1, W2, (float*)p_h2, nullptr, b2, n, HDIM, HDIM);

    // final dot + sigmoid
    k_final<<<(n + 7) / 8, 256>>>(W3, b3, out, n);
}

// round 3
// speedup vs baseline: 1.4192x; 1.4192x over previous
#include <cuda_runtime.h>
#include <stdint.h>

#define NN      100000
#define FDIM    128
#define HDIM    256
#define EMAX    1800000
#define NEG_SLOPE 0.2f
#define SCAN_T  512

// -------- scratch (static device arrays; no runtime malloc) ----------
__device__ float g_h   [(size_t)NN * FDIM];   // h = x @ W
__device__ float g_asrc[NN];
__device__ float g_adst[NN];
__device__ float g_gat [(size_t)NN * FDIM];   // GAT output
__device__ float g_h1  [(size_t)NN * HDIM];
__device__ float g_h2  [(size_t)NN * HDIM];
__device__ int   g_src [EMAX];                // flat edge endpoints (incl. self loops)
__device__ int   g_dst [EMAX];
__device__ int   g_csrc[EMAX];                // CSR: src ids grouped by dst
__device__ int   g_cnt [NN];                  // histogram
__device__ int   g_cnt2[NN];                  // slot counters
__device__ int   g_rp  [NN + 1];              // CSR row pointers
__device__ int   g_part[256];                 // scan partials
__device__ int   g_is64;

// --------------------------- dtype probe ---------------------------
__global__ void k_detect(const int* __restrict__ ei, int E) {
    __shared__ int nz;
    if (threadIdx.x == 0) nz = 0;
    __syncthreads();
    int samples = 4096;
    if (samples > E) samples = E;
    for (int i = threadIdx.x; i < samples; i += blockDim.x)
        if (ei[2 * i + 1] != 0) atomicOr(&nz, 1);
    __syncthreads();
    if (threadIdx.x == 0) g_is64 = (nz == 0) ? 1 : 0;
}

// ----------------- edge expansion (+ self loops) -------------------
__global__ void k_convert(const int* __restrict__ ei, int E, int n) {
    int tot = E + n;
    int stride = gridDim.x * blockDim.x;
    int is64 = g_is64;
    for (int idx = blockIdx.x * blockDim.x + threadIdx.x; idx < tot; idx += stride) {
        int s, d;
        if (idx < E) {
            if (is64) { s = ei[2 * idx]; d = ei[2 * E + 2 * idx]; }
            else      { s = ei[idx];     d = ei[E + idx]; }
        } else {
            s = d = idx - E;
        }
        g_src[idx] = s;
        g_dst[idx] = d;
    }
}

__global__ void k_zero(int n) {
    int stride = gridDim.x * blockDim.x;
    for (int i = blockIdx.x * blockDim.x + threadIdx.x; i < n; i += stride) {
        g_cnt[i] = 0; g_cnt2[i] = 0;
    }
}

__global__ void k_hist(int tot) {
    int stride = gridDim.x * blockDim.x;
    for (int i = blockIdx.x * blockDim.x + threadIdx.x; i < tot; i += stride)
        atomicAdd(&g_cnt[g_dst[i]], 1);
}

// ------------------------ hierarchical scan ------------------------
__global__ void k_scan1(int n) {
    __shared__ int sh[SCAN_T];
    int t = threadIdx.x;
    int i = blockIdx.x * SCAN_T + t;
    int v = (i < n) ? g_cnt[i] : 0;
    sh[t] = v;
    __syncthreads();
    for (int o = 1; o < SCAN_T; o <<= 1) {
        int x = (t >= o) ? sh[t - o] : 0;
        __syncthreads();
        sh[t] += x;
        __syncthreads();
    }
    if (i < n) g_rp[i] = sh[t] - v;            // block-local exclusive
    if (t == SCAN_T - 1) g_part[blockIdx.x] = sh[t];
}

__global__ void k_scan2(int nb) {              // single block, nb <= 256
    __shared__ int sh[256];
    int t = threadIdx.x;
    int v = (t < nb) ? g_part[t] : 0;
    sh[t] = v;
    __syncthreads();
    for (int o = 1; o < 256; o <<= 1) {
        int x = (t >= o) ? sh[t - o] : 0;
        __syncthreads();
        sh[t] += x;
        __syncthreads();
    }
    if (t < nb) g_part[t] = sh[t] - v;         // exclusive
}

__global__ void k_scan3(int n, int etot) {
    int i = blockIdx.x * SCAN_T + threadIdx.x;
    if (i < n) g_rp[i] += g_part[blockIdx.x];
    if (i == 0) g_rp[n] = etot;
}

__global__ void k_slot(int tot) {
    int stride = gridDim.x * blockDim.x;
    for (int i = blockIdx.x * blockDim.x + threadIdx.x; i < tot; i += stride) {
        int d = g_dst[i];
        int slot = g_rp[d] + atomicAdd(&g_cnt2[d], 1);
        g_csrc[slot] = g_src[i];
    }
}

// ----------- sgemm (fp32, 128x128x16, 8x8/thread, double-buffered) --------
template<bool RELU, bool ABIAS, bool CBIAS>
__global__ void __launch_bounds__(256) k_sgemm(
    const float* __restrict__ A, const float* __restrict__ B,
    float* __restrict__ C,
    const float* __restrict__ abias,   // added along K to A rows
    const float* __restrict__ cbias,   // added along N to C
    int M, int N, int K)
{
    constexpr int BM = 128, BN = 128, BK = 16;
    __shared__ float As[2][BK][BM];
    __shared__ float Bs[2][BK][BN];

    const int tid = threadIdx.x;
    const int tr = tid >> 4;
    const int tc = tid & 15;
    const int rowBase = blockIdx.y * BM;
    const int colBase = blockIdx.x * BN;

    // per-thread load coordinates
    const int ar0 = tid >> 2,        ac0 = (tid & 3) * 4;        // A slot 0
    const int ar1 = (tid + 256) >> 2, ac1 = ((tid + 256) & 3) * 4;
    const int br0 = tid >> 5,        bc0 = (tid & 31) * 4;       // B slot 0
    const int br1 = (tid + 256) >> 5, bc1 = ((tid + 256) & 31) * 4;

    float acc[8][8];
#pragma unroll
    for (int i = 0; i < 8; i++)
#pragma unroll
        for (int j = 0; j < 8; j++) acc[i][j] = 0.f;

    // ---- prefetch first tile into registers
    float4 pa0, pa1, pb0, pb1;
    {
        int gr0 = rowBase + ar0, gr1 = rowBase + ar1;
        pa0 = make_float4(0.f, 0.f, 0.f, 0.f);
        pa1 = make_float4(0.f, 0.f, 0.f, 0.f);
        if (gr0 < M) pa0 = *(const float4*)(A + (size_t)gr0 * K + ac0);
        if (gr1 < M) pa1 = *(const float4*)(A + (size_t)gr1 * K + ac1);
        if (ABIAS) {
            float4 b0 = *(const float4*)(abias + ac0);
            float4 b1 = *(const float4*)(abias + ac1);
            if (gr0 < M) { pa0.x += b0.x; pa0.y += b0.y; pa0.z += b0.z; pa0.w += b0.w; }
            if (gr1 < M) { pa1.x += b1.x; pa1.y += b1.y; pa1.z += b1.z; pa1.w += b1.w; }
        }
        pb0 = *(const float4*)(B + (size_t)br0 * N + colBase + bc0);
        pb1 = *(const float4*)(B + (size_t)br1 * N + colBase + bc1);
    }
    // store tile 0
    As[0][ac0 + 0][ar0] = pa0.x; As[0][ac0 + 1][ar0] = pa0.y;
    As[0][ac0 + 2][ar0] = pa0.z; As[0][ac0 + 3][ar0] = pa0.w;
    As[0][ac1 + 0][ar1] = pa1.x; As[0][ac1 + 1][ar1] = pa1.y;
    As[0][ac1 + 2][ar1] = pa1.z; As[0][ac1 + 3][ar1] = pa1.w;
    *(float4*)&Bs[0][br0][bc0] = pb0;
    *(float4*)&Bs[0][br1][bc1] = pb1;
    __syncthreads();

    int buf = 0;
    for (int k0 = 0; k0 < K; k0 += BK) {
        const bool has_next = (k0 + BK) < K;
        if (has_next) {
            int kn = k0 + BK;
            int gr0 = rowBase + ar0, gr1 = rowBase + ar1;
            pa0 = make_float4(0.f, 0.f, 0.f, 0.f);
            pa1 = make_float4(0.f, 0.f, 0.f, 0.f);
            if (gr0 < M) pa0 = *(const float4*)(A + (size_t)gr0 * K + kn + ac0);
            if (gr1 < M) pa1 = *(const float4*)(A + (size_t)gr1 * K + kn + ac1);
            if (ABIAS) {
                float4 b0 = *(const float4*)(abias + kn + ac0);
                float4 b1 = *(const float4*)(abias + kn + ac1);
                if (gr0 < M) { pa0.x += b0.x; pa0.y += b0.y; pa0.z += b0.z; pa0.w += b0.w; }
                if (gr1 < M) { pa1.x += b1.x; pa1.y += b1.y; pa1.z += b1.z; pa1.w += b1.w; }
            }
            pb0 = *(const float4*)(B + (size_t)(kn + br0) * N + colBase + bc0);
            pb1 = *(const float4*)(B + (size_t)(kn + br1) * N + colBase + bc1);
        }

#pragma unroll
        for (int kk = 0; kk < BK; kk++) {
            float a[8], b[8];
            *(float4*)&a[0] = *(float4*)&As[buf][kk][tr * 8];
            *(float4*)&a[4] = *(float4*)&As[buf][kk][tr * 8 + 4];
            *(float4*)&b[0] = *(float4*)&Bs[buf][kk][tc * 8];
            *(float4*)&b[4] = *(float4*)&Bs[buf][kk][tc * 8 + 4];
#pragma unroll
            for (int i = 0; i < 8; i++)
#pragma unroll
                for (int j = 0; j < 8; j++)
                    acc[i][j] += a[i] * b[j];
        }

        if (has_next) {
            int nb = buf ^ 1;
            As[nb][ac0 + 0][ar0] = pa0.x; As[nb][ac0 + 1][ar0] = pa0.y;
            As[nb][ac0 + 2][ar0] = pa0.z; As[nb][ac0 + 3][ar0] = pa0.w;
            As[nb][ac1 + 0][ar1] = pa1.x; As[nb][ac1 + 1][ar1] = pa1.y;
            As[nb][ac1 + 2][ar1] = pa1.z; As[nb][ac1 + 3][ar1] = pa1.w;
            *(float4*)&Bs[nb][br0][bc0] = pb0;
            *(float4*)&Bs[nb][br1][bc1] = pb1;
            __syncthreads();
            buf = nb;
        }
    }

    // ---- epilogue
#pragma unroll
    for (int i = 0; i < 8; i++) {
        int gr = rowBase + tr * 8 + i;
        if (gr >= M) continue;
#pragma unroll
        for (int j4 = 0; j4 < 2; j4++) {
            int gc = colBase + tc * 8 + j4 * 4;
            float4 v;
            v.x = acc[i][j4 * 4 + 0];
            v.y = acc[i][j4 * 4 + 1];
            v.z = acc[i][j4 * 4 + 2];
            v.w = acc[i][j4 * 4 + 3];
            if (CBIAS) {
                float4 bb = *(const float4*)(cbias + gc);
                v.x += bb.x; v.y += bb.y; v.z += bb.z; v.w += bb.w;
            }
            if (RELU) {
                v.x = fmaxf(v.x, 0.f); v.y = fmaxf(v.y, 0.f);
                v.z = fmaxf(v.z, 0.f); v.w = fmaxf(v.w, 0.f);
            }
            *(float4*)(C + (size_t)gr * N + gc) = v;
        }
    }
}

// ----------------------- per-node attention dots --------------------------
__global__ void k_att(const float* __restrict__ att_src,
                      const float* __restrict__ att_dst, int n) {
    int w = (blockIdx.x * blockDim.x + threadIdx.x) >> 5;
    int lane = threadIdx.x & 31;
    if (w >= n) return;
    float4 hv = ((const float4*)(g_h + (size_t)w * FDIM))[lane];
    float4 as = ((const float4*)att_src)[lane];
    float4 ad = ((const float4*)att_dst)[lane];
    float s = hv.x * as.x + hv.y * as.y + hv.z * as.z + hv.w * as.w;
    float d = hv.x * ad.x + hv.y * ad.y + hv.z * ad.z + hv.w * ad.w;
#pragma unroll
    for (int o = 16; o; o >>= 1) {
        s += __shfl_xor_sync(0xFFFFFFFFu, s, o);
        d += __shfl_xor_sync(0xFFFFFFFFu, d, o);
    }
    if (lane == 0) { g_asrc[w] = s; g_adst[w] = d; }
}

// --------- fused per-node softmax + aggregation (warp per dst) ------------
__global__ void k_gather(int n) {
    int w = (blockIdx.x * blockDim.x + threadIdx.x) >> 5;
    int lane = threadIdx.x & 31;
    if (w >= n) return;

    int base = g_rp[w];
    int deg  = g_rp[w + 1] - base;
    float adst = g_adst[w];

    // pass 1: online softmax stats (lane-parallel over edges)
    float m_l = -3.4e38f, z_l = 0.f;
    for (int j = lane; j < deg; j += 32) {
        int s = g_csrc[base + j];
        float e = g_asrc[s] + adst;
        e = (e > 0.f) ? e : NEG_SLOPE * e;
        float mn = fmaxf(m_l, e);
        z_l = z_l * __expf(m_l - mn) + __expf(e - mn);
        m_l = mn;
    }
#pragma unroll
    for (int o = 16; o; o >>= 1) {
        float mo = __shfl_xor_sync(0xFFFFFFFFu, m_l, o);
        float zo = __shfl_xor_sync(0xFFFFFFFFu, z_l, o);
        float mn = fmaxf(m_l, mo);
        z_l = z_l * __expf(m_l - mn) + zo * __expf(mo - mn);
        m_l = mn;
    }
    float m = m_l;
    float inv_z = 1.f / z_l;

    // pass 2: accumulate alpha * h[src]; each lane owns features [lane*4, lane*4+4)
    float4 acc = make_float4(0.f, 0.f, 0.f, 0.f);
    for (int j0 = 0; j0 < deg; j0 += 32) {
        int j = j0 + lane;
        int s = 0; float wgt = 0.f;
        if (j < deg) {
            s = g_csrc[base + j];
            float e = g_asrc[s] + adst;
            e = (e > 0.f) ? e : NEG_SLOPE * e;
            wgt = __expf(e - m);
        }
        int cnt = deg - j0; if (cnt > 32) cnt = 32;
        for (int jj = 0; jj < cnt; jj++) {
            int   ss = __shfl_sync(0xFFFFFFFFu, s,   jj);
            float ww = __shfl_sync(0xFFFFFFFFu, wgt, jj);
            float4 v = ((const float4*)(g_h + (size_t)ss * FDIM))[lane];
            acc.x += ww * v.x; acc.y += ww * v.y;
            acc.z += ww * v.z; acc.w += ww * v.w;
        }
    }
    acc.x *= inv_z; acc.y *= inv_z; acc.z *= inv_z; acc.w *= inv_z;
    ((float4*)(g_gat + (size_t)w * FDIM))[lane] = acc;
}

// ----------------------- final 256->1 + sigmoid ---------------------------
__global__ void k_final(const float* __restrict__ W3,
                        const float* __restrict__ b3,
                        float* __restrict__ out, int n) {
    int w = (blockIdx.x * blockDim.x + threadIdx.x) >> 5;
    int lane = threadIdx.x & 31;
    if (w >= n) return;
    const float4* hp = (const float4*)(g_h2 + (size_t)w * HDIM);
    const float4* wp = (const float4*)W3;
    float acc = 0.f;
#pragma unroll
    for (int j = 0; j < 2; j++) {
        float4 h = hp[lane + 32 * j];
        float4 ww = wp[lane + 32 * j];
        acc += h.x * ww.x + h.y * ww.y + h.z * ww.z + h.w * ww.w;
    }
#pragma unroll
    for (int o = 16; o; o >>= 1) acc += __shfl_xor_sync(0xFFFFFFFFu, acc, o);
    if (lane == 0) out[w] = 1.f / (1.f + expf(-(acc + b3[0])));
}

// --------------------------- host launcher --------------------------------
extern "C" void kernel_launch(void* const* d_in, const int* in_sizes, int n_in,
                              void* d_out, int out_size) {
    const float* x       = (const float*)d_in[0];
    const int*   ei      = (const int*)d_in[1];
    const float* W       = (const float*)d_in[2];
    const float* att_src = (const float*)d_in[3];
    const float* att_dst = (const float*)d_in[4];
    const float* bias    = (const float*)d_in[5];
    const float* W1      = (const float*)d_in[6];
    const float* b1      = (const float*)d_in[7];
    const float* W2      = (const float*)d_in[8];
    const float* b2      = (const float*)d_in[9];
    const float* W3      = (const float*)d_in[10];
    const float* b3      = (const float*)d_in[11];
    float* out = (float*)d_out;

    int n = in_sizes[0] / FDIM;     // 100000
    int E = in_sizes[1] / 2;        // 1600000
    int Etot = E + n;
    int scanBlocks = (n + SCAN_T - 1) / SCAN_T;

    void *p_h, *p_gat, *p_h1, *p_h2;
    cudaGetSymbolAddress(&p_h,   g_h);
    cudaGetSymbolAddress(&p_gat, g_gat);
    cudaGetSymbolAddress(&p_h1,  g_h1);
    cudaGetSymbolAddress(&p_h2,  g_h2);

    int mBlocks = (n + 127) / 128;

    // CSR build
    k_detect<<<1, 256>>>(ei, E);
    k_convert<<<2048, 256>>>(ei, E, n);
    k_zero<<<512, 256>>>(n);
    k_hist<<<2048, 256>>>(Etot);
    k_scan1<<<scanBlocks, SCAN_T>>>(n);

    // h = x @ W  (independent; placed here, also as the ncu -s 5 capture target)
    k_sgemm<false, false, false><<<dim3(1, mBlocks), 256>>>(
        x, W, (float*)p_h, nullptr, nullptr, n, FDIM, FDIM);

    k_scan2<<<1, 256>>>(scanBlocks);
    k_scan3<<<scanBlocks, SCAN_T>>>(n, Etot);
    k_slot<<<2048, 256>>>(Etot);

    // attention dots
    k_att<<<(n + 7) / 8, 256>>>(att_src, att_dst, n);

    // fused softmax + aggregation
    k_gather<<<(n + 7) / 8, 256>>>(n);

    // MLP
    k_sgemm<true, true, true><<<dim3(2, mBlocks), 256>>>(
        (const float*)p_gat, W1, (float*)p_h1, bias, b1, n, HDIM, FDIM);
    k_sgemm<true, false, true><<<dim3(2, mBlocks), 256>>>(
        (const float*)p_h1, W2, (float*)p_h2, nullptr, b2, n, HDIM, HDIM);
    k_final<<<(n + 7) / 8, 256>>>(W3, b3, out, n);
}

// round 5
// speedup vs baseline: 1.7084x; 1.2038x over previous
#include <cuda_runtime.h>
#include <stdint.h>

#define NN      100000
#define FDIM    128
#define HDIM    256
#define EMAX    1800000
#define NEG_SLOPE 0.2f
#define SCAN_T  512

// dynamic smem: 2 stages x (Ah,Al,Bh,Bl each 16x128 floats) = 2*8192 floats
#define STAGE_F 8192
#define SMEM_BYTES (2 * STAGE_F * 4)

// -------- scratch (static device arrays; no runtime malloc) ----------
__device__ float g_h   [(size_t)NN * FDIM];
__device__ float g_asrc[NN];
__device__ float g_adst[NN];
__device__ float g_gat [(size_t)NN * FDIM];
__device__ float g_h1  [(size_t)NN * HDIM];
__device__ float g_h2  [(size_t)NN * HDIM];
__device__ int   g_src [EMAX];
__device__ int   g_dst [EMAX];
__device__ int   g_csrc[EMAX];
__device__ int   g_cnt [NN];
__device__ int   g_cnt2[NN];
__device__ int   g_rp  [NN + 1];
__device__ int   g_part[256];
__device__ int   g_is64;

// --------------------------- dtype probe ---------------------------
__global__ void k_detect(const int* __restrict__ ei, int E) {
    __shared__ int nz;
    if (threadIdx.x == 0) nz = 0;
    __syncthreads();
    int samples = 4096;
    if (samples > E) samples = E;
    for (int i = threadIdx.x; i < samples; i += blockDim.x)
        if (ei[2 * i + 1] != 0) atomicOr(&nz, 1);
    __syncthreads();
    if (threadIdx.x == 0) g_is64 = (nz == 0) ? 1 : 0;
}

// ----------------- edge expansion (+ self loops) -------------------
__global__ void k_convert(const int* __restrict__ ei, int E, int n) {
    int tot = E + n;
    int stride = gridDim.x * blockDim.x;
    int is64 = g_is64;
    for (int idx = blockIdx.x * blockDim.x + threadIdx.x; idx < tot; idx += stride) {
        int s, d;
        if (idx < E) {
            if (is64) { s = ei[2 * idx]; d = ei[2 * E + 2 * idx]; }
            else      { s = ei[idx];     d = ei[E + idx]; }
        } else {
            s = d = idx - E;
        }
        g_src[idx] = s;
        g_dst[idx] = d;
    }
}

__global__ void k_zero(int n) {
    int stride = gridDim.x * blockDim.x;
    for (int i = blockIdx.x * blockDim.x + threadIdx.x; i < n; i += stride) {
        g_cnt[i] = 0; g_cnt2[i] = 0;
    }
}

__global__ void k_hist(int tot) {
    int stride = gridDim.x * blockDim.x;
    for (int i = blockIdx.x * blockDim.x + threadIdx.x; i < tot; i += stride)
        atomicAdd(&g_cnt[g_dst[i]], 1);
}

// ------------------------ hierarchical scan ------------------------
__global__ void k_scan1(int n) {
    __shared__ int sh[SCAN_T];
    int t = threadIdx.x;
    int i = blockIdx.x * SCAN_T + t;
    int v = (i < n) ? g_cnt[i] : 0;
    sh[t] = v;
    __syncthreads();
    for (int o = 1; o < SCAN_T; o <<= 1) {
        int x = (t >= o) ? sh[t - o] : 0;
        __syncthreads();
        sh[t] += x;
        __syncthreads();
    }
    if (i < n) g_rp[i] = sh[t] - v;
    if (t == SCAN_T - 1) g_part[blockIdx.x] = sh[t];
}

__global__ void k_scan2(int nb) {
    __shared__ int sh[256];
    int t = threadIdx.x;
    int v = (t < nb) ? g_part[t] : 0;
    sh[t] = v;
    __syncthreads();
    for (int o = 1; o < 256; o <<= 1) {
        int x = (t >= o) ? sh[t - o] : 0;
        __syncthreads();
        sh[t] += x;
        __syncthreads();
    }
    if (t < nb) g_part[t] = sh[t] - v;
}

__global__ void k_scan3(int n, int etot) {
    int i = blockIdx.x * SCAN_T + threadIdx.x;
    if (i < n) g_rp[i] += g_part[blockIdx.x];
    if (i == 0) g_rp[n] = etot;
}

__global__ void k_slot(int tot) {
    int stride = gridDim.x * blockDim.x;
    for (int i = blockIdx.x * blockDim.x + threadIdx.x; i < tot; i += stride) {
        int d = g_dst[i];
        int slot = g_rp[d] + atomicAdd(&g_cnt2[d], 1);
        g_csrc[slot] = g_src[i];
    }
}

// --------------------------- tf32 helpers ---------------------------
__device__ __forceinline__ unsigned tf32_rna(float v) {
    unsigned r;
    asm("cvt.rna.tf32.f32 %0, %1;" : "=r"(r) : "f"(v));
    return r;
}

__device__ __forceinline__ void mma_tf32(float c[4],
                                         unsigned a0, unsigned a1, unsigned a2, unsigned a3,
                                         unsigned b0, unsigned b1) {
    asm volatile(
        "mma.sync.aligned.m16n8k8.row.col.f32.tf32.tf32.f32 "
        "{%0,%1,%2,%3}, {%4,%5,%6,%7}, {%8,%9}, {%0,%1,%2,%3};"
        : "+f"(c[0]), "+f"(c[1]), "+f"(c[2]), "+f"(c[3])
        : "r"(a0), "r"(a1), "r"(a2), "r"(a3), "r"(b0), "r"(b1));
}

// ---------------- tensor-core GEMM: tf32x3, 128x128 block, BK=16 ----------
// 8 warps, each computes a 32x64 warp tile (2 x 8 m16n8 frags).
// smem planes per stage: Ah/Al as [k][m] (XOR swizz), Bh/Bl as [k][n] (XOR swizz).
template<bool RELU, bool ABIAS, bool CBIAS>
__global__ void __launch_bounds__(256) k_mma(
    const float* __restrict__ A, const float* __restrict__ B,
    float* __restrict__ C,
    const float* __restrict__ abias, const float* __restrict__ cbias,
    int M, int N, int K)
{
    extern __shared__ float sm[];

    const int tid  = threadIdx.x;
    const int wid  = tid >> 5;
    const int lane = tid & 31;
    const int gid  = lane >> 2;     // 0..7
    const int tig  = lane & 3;      // 0..3
    const int warpM = (wid & 3) * 32;
    const int warpN = (wid >> 2) * 64;
    const int rowBase = blockIdx.y * 128;
    const int colBase = blockIdx.x * 128;

    // loader coordinates (2 slots each for A and B; 512 float4 per tile)
    const int ar0 = tid >> 2,  ac0 = (tid & 3) * 4;   // A: row m, col k
    const int ar1 = ar0 + 64;
    const int br0 = tid >> 5,  bc0 = (tid & 31) * 4;  // B: row k, col n
    const int br1 = br0 + 8;

    float acc[2][8][4];
#pragma unroll
    for (int mf = 0; mf < 2; mf++)
#pragma unroll
        for (int nf = 0; nf < 8; nf++)
#pragma unroll
            for (int r = 0; r < 4; r++) acc[mf][nf][r] = 0.f;

    float4 pa0, pa1, pb0, pb1;

    auto gload = [&](int k0) {
        int gr0 = rowBase + ar0, gr1 = rowBase + ar1;
        pa0 = make_float4(0.f, 0.f, 0.f, 0.f);
        pa1 = make_float4(0.f, 0.f, 0.f, 0.f);
        if (gr0 < M) pa0 = *(const float4*)(A + (size_t)gr0 * K + k0 + ac0);
        if (gr1 < M) pa1 = *(const float4*)(A + (size_t)gr1 * K + k0 + ac0);
        if (ABIAS) {
            float4 bb = *(const float4*)(abias + k0 + ac0);
            if (gr0 < M) { pa0.x += bb.x; pa0.y += bb.y; pa0.z += bb.z; pa0.w += bb.w; }
            if (gr1 < M) { pa1.x += bb.x; pa1.y += bb.y; pa1.z += bb.z; pa1.w += bb.w; }
        }
        pb0 = *(const float4*)(B + (size_t)(k0 + br0) * N + colBase + bc0);
        pb1 = *(const float4*)(B + (size_t)(k0 + br1) * N + colBase + bc0);
    };

    auto gstore = [&](int buf) {
        float* Ah = sm + buf * STAGE_F;
        float* Al = Ah + 2048;
        float* Bh = Ah + 4096;
        float* Bl = Ah + 6144;
        float va0[4] = {pa0.x, pa0.y, pa0.z, pa0.w};
        float va1[4] = {pa1.x, pa1.y, pa1.z, pa1.w};
#pragma unroll
        for (int j = 0; j < 4; j++) {
            int k = ac0 + j;
            int sw = j * 8;                    // (k&3)*8, since ac0 % 4 == 0
            unsigned h0 = tf32_rna(va0[j]);
            unsigned l0 = tf32_rna(va0[j] - __uint_as_float(h0));
            Ah[k * 128 + (ar0 ^ sw)] = __uint_as_float(h0);
            Al[k * 128 + (ar0 ^ sw)] = __uint_as_float(l0);
            unsigned h1 = tf32_rna(va1[j]);
            unsigned l1 = tf32_rna(va1[j] - __uint_as_float(h1));
            Ah[k * 128 + (ar1 ^ sw)] = __uint_as_float(h1);
            Al[k * 128 + (ar1 ^ sw)] = __uint_as_float(l1);
        }
        // B: float4 stores, conflict-free
        {
            int pc0 = bc0 ^ ((br0 & 3) * 8);
            int pc1 = bc0 ^ ((br1 & 3) * 8);
            float4 vh, vl;
            unsigned h;
            h = tf32_rna(pb0.x); vh.x = __uint_as_float(h); vl.x = __uint_as_float(tf32_rna(pb0.x - __uint_as_float(h)));
            h = tf32_rna(pb0.y); vh.y = __uint_as_float(h); vl.y = __uint_as_float(tf32_rna(pb0.y - __uint_as_float(h)));
            h = tf32_rna(pb0.z); vh.z = __uint_as_float(h); vl.z = __uint_as_float(tf32_rna(pb0.z - __uint_as_float(h)));
            h = tf32_rna(pb0.w); vh.w = __uint_as_float(h); vl.w = __uint_as_float(tf32_rna(pb0.w - __uint_as_float(h)));
            *(float4*)&Bh[br0 * 128 + pc0] = vh;
            *(float4*)&Bl[br0 * 128 + pc0] = vl;
            h = tf32_rna(pb1.x); vh.x = __uint_as_float(h); vl.x = __uint_as_float(tf32_rna(pb1.x - __uint_as_float(h)));
            h = tf32_rna(pb1.y); vh.y = __uint_as_float(h); vl.y = __uint_as_float(tf32_rna(pb1.y - __uint_as_float(h)));
            h = tf32_rna(pb1.z); vh.z = __uint_as_float(h); vl.z = __uint_as_float(tf32_rna(pb1.z - __uint_as_float(h)));
            h = tf32_rna(pb1.w); vh.w = __uint_as_float(h); vl.w = __uint_as_float(tf32_rna(pb1.w - __uint_as_float(h)));
            *(float4*)&Bh[br1 * 128 + pc1] = vh;
            *(float4*)&Bl[br1 * 128 + pc1] = vl;
        }
    };

    // prefetch + store first tile
    gload(0);
    gstore(0);
    __syncthreads();

    int buf = 0;
    for (int k0 = 0; k0 < K; k0 += 16) {
        const bool has_next = (k0 + 16) < K;
        if (has_next) gload(k0 + 16);

        const float* Ah = sm + buf * STAGE_F;
        const float* Al = Ah + 2048;
        const float* Bh = Ah + 4096;
        const float* Bl = Ah + 6144;

#pragma unroll
        for (int ks = 0; ks < 2; ks++) {
            const int kO = ks * 8;
            const int sw = tig * 8;
            const int kr0 = (kO + tig) * 128;
            const int kr1 = (kO + tig + 4) * 128;

            unsigned ah[2][4], al[2][4];
#pragma unroll
            for (int mf = 0; mf < 2; mf++) {
                int m0 = warpM + mf * 16 + gid;
                int m1 = m0 + 8;
                ah[mf][0] = __float_as_uint(Ah[kr0 + (m0 ^ sw)]);
                ah[mf][1] = __float_as_uint(Ah[kr0 + (m1 ^ sw)]);
                ah[mf][2] = __float_as_uint(Ah[kr1 + (m0 ^ sw)]);
                ah[mf][3] = __float_as_uint(Ah[kr1 + (m1 ^ sw)]);
                al[mf][0] = __float_as_uint(Al[kr0 + (m0 ^ sw)]);
                al[mf][1] = __float_as_uint(Al[kr0 + (m1 ^ sw)]);
                al[mf][2] = __float_as_uint(Al[kr1 + (m0 ^ sw)]);
                al[mf][3] = __float_as_uint(Al[kr1 + (m1 ^ sw)]);
            }
#pragma unroll
            for (int nf = 0; nf < 8; nf++) {
                int n = warpN + nf * 8 + gid;
                int pc = n ^ sw;
                unsigned bh0 = __float_as_uint(Bh[kr0 + pc]);
                unsigned bh1 = __float_as_uint(Bh[kr1 + pc]);
                unsigned bl0 = __float_as_uint(Bl[kr0 + pc]);
                unsigned bl1 = __float_as_uint(Bl[kr1 + pc]);
#pragma unroll
                for (int mf = 0; mf < 2; mf++) {
                    mma_tf32(acc[mf][nf], al[mf][0], al[mf][1], al[mf][2], al[mf][3], bh0, bh1);
                    mma_tf32(acc[mf][nf], ah[mf][0], ah[mf][1], ah[mf][2], ah[mf][3], bl0, bl1);
                    mma_tf32(acc[mf][nf], ah[mf][0], ah[mf][1], ah[mf][2], ah[mf][3], bh0, bh1);
                }
            }
        }

        if (has_next) {
            int nb = buf ^ 1;
            // writes below target nb, whose last readers were iteration k0-16,
            // already separated by the barrier at the end of that iteration.
            gstore(nb);
            __syncthreads();
            buf = nb;
        }
    }

    // ---- epilogue: float2 stores
#pragma unroll
    for (int mf = 0; mf < 2; mf++) {
        int r0 = rowBase + warpM + mf * 16 + gid;
        int r1 = r0 + 8;
#pragma unroll
        for (int nf = 0; nf < 8; nf++) {
            int gc = colBase + warpN + nf * 8 + tig * 2;
            float v0 = acc[mf][nf][0], v1 = acc[mf][nf][1];
            float v2 = acc[mf][nf][2], v3 = acc[mf][nf][3];
            if (CBIAS) {
                float2 bb = *(const float2*)(cbias + gc);
                v0 += bb.x; v1 += bb.y; v2 += bb.x; v3 += bb.y;
            }
            if (RELU) {
                v0 = fmaxf(v0, 0.f); v1 = fmaxf(v1, 0.f);
                v2 = fmaxf(v2, 0.f); v3 = fmaxf(v3, 0.f);
            }
            if (r0 < M) { float2 o = {v0, v1}; *(float2*)(C + (size_t)r0 * N + gc) = o; }
            if (r1 < M) { float2 o = {v2, v3}; *(float2*)(C + (size_t)r1 * N + gc) = o; }
        }
    }
}

// ----------------------- per-node attention dots --------------------------
__global__ void k_att(const float* __restrict__ att_src,
                      const float* __restrict__ att_dst, int n) {
    int w = (blockIdx.x * blockDim.x + threadIdx.x) >> 5;
    int lane = threadIdx.x & 31;
    if (w >= n) return;
    float4 hv = ((const float4*)(g_h + (size_t)w * FDIM))[lane];
    float4 as = ((const float4*)att_src)[lane];
    float4 ad = ((const float4*)att_dst)[lane];
    float s = hv.x * as.x + hv.y * as.y + hv.z * as.z + hv.w * as.w;
    float d = hv.x * ad.x + hv.y * ad.y + hv.z * ad.z + hv.w * ad.w;
#pragma unroll
    for (int o = 16; o; o >>= 1) {
        s += __shfl_xor_sync(0xFFFFFFFFu, s, o);
        d += __shfl_xor_sync(0xFFFFFFFFu, d, o);
    }
    if (lane == 0) { g_asrc[w] = s; g_adst[w] = d; }
}

// --------- fused per-node softmax + aggregation (warp per dst) ------------
__global__ void k_gather(int n) {
    int w = (blockIdx.x * blockDim.x + threadIdx.x) >> 5;
    int lane = threadIdx.x & 31;
    if (w >= n) return;

    int base = g_rp[w];
    int deg  = g_rp[w + 1] - base;
    float adst = g_adst[w];

    float m_l = -3.4e38f, z_l = 0.f;
    for (int j = lane; j < deg; j += 32) {
        int s = g_csrc[base + j];
        float e = g_asrc[s] + adst;
        e = (e > 0.f) ? e : NEG_SLOPE * e;
        float mn = fmaxf(m_l, e);
        z_l = z_l * __expf(m_l - mn) + __expf(e - mn);
        m_l = mn;
    }
#pragma unroll
    for (int o = 16; o; o >>= 1) {
        float mo = __shfl_xor_sync(0xFFFFFFFFu, m_l, o);
        float zo = __shfl_xor_sync(0xFFFFFFFFu, z_l, o);
        float mn = fmaxf(m_l, mo);
        z_l = z_l * __expf(m_l - mn) + zo * __expf(mo - mn);
        m_l = mn;
    }
    float m = m_l;
    float inv_z = 1.f / z_l;

    float4 acc = make_float4(0.f, 0.f, 0.f, 0.f);
    for (int j0 = 0; j0 < deg; j0 += 32) {
        int j = j0 + lane;
        int s = 0; float wgt = 0.f;
        if (j < deg) {
            s = g_csrc[base + j];
            float e = g_asrc[s] + adst;
            e = (e > 0.f) ? e : NEG_SLOPE * e;
            wgt = __expf(e - m);
        }
        int cnt = deg - j0; if (cnt > 32) cnt = 32;
        for (int jj = 0; jj < cnt; jj++) {
            int   ss = __shfl_sync(0xFFFFFFFFu, s,   jj);
            float ww = __shfl_sync(0xFFFFFFFFu, wgt, jj);
            float4 v = ((const float4*)(g_h + (size_t)ss * FDIM))[lane];
            acc.x += ww * v.x; acc.y += ww * v.y;
            acc.z += ww * v.z; acc.w += ww * v.w;
        }
    }
    acc.x *= inv_z; acc.y *= inv_z; acc.z *= inv_z; acc.w *= inv_z;
    ((float4*)(g_gat + (size_t)w * FDIM))[lane] = acc;
}

// ----------------------- final 256->1 + sigmoid ---------------------------
__global__ void k_final(const float* __restrict__ W3,
                        const float* __restrict__ b3,
                        float* __restrict__ out, int n) {
    int w = (blockIdx.x * blockDim.x + threadIdx.x) >> 5;
    int lane = threadIdx.x & 31;
    if (w >= n) return;
    const float4* hp = (const float4*)(g_h2 + (size_t)w * HDIM);
    const float4* wp = (const float4*)W3;
    float acc = 0.f;
#pragma unroll
    for (int j = 0; j < 2; j++) {
        float4 h = hp[lane + 32 * j];
        float4 ww = wp[lane + 32 * j];
        acc += h.x * ww.x + h.y * ww.y + h.z * ww.z + h.w * ww.w;
    }
#pragma unroll
    for (int o = 16; o; o >>= 1) acc += __shfl_xor_sync(0xFFFFFFFFu, acc, o);
    if (lane == 0) out[w] = 1.f / (1.f + expf(-(acc + b3[0])));
}

// --------------------------- host launcher --------------------------------
extern "C" void kernel_launch(void* const* d_in, const int* in_sizes, int n_in,
                              void* d_out, int out_size) {
    const float* x       = (const float*)d_in[0];
    const int*   ei      = (const int*)d_in[1];
    const float* W       = (const float*)d_in[2];
    const float* att_src = (const float*)d_in[3];
    const float* att_dst = (const float*)d_in[4];
    const float* bias    = (const float*)d_in[5];
    const float* W1      = (const float*)d_in[6];
    const float* b1      = (const float*)d_in[7];
    const float* W2      = (const float*)d_in[8];
    const float* b2      = (const float*)d_in[9];
    const float* W3      = (const float*)d_in[10];
    const float* b3      = (const float*)d_in[11];
    float* out = (float*)d_out;

    int n = in_sizes[0] / FDIM;
    int E = in_sizes[1] / 2;
    int Etot = E + n;
    int scanBlocks = (n + SCAN_T - 1) / SCAN_T;

    void *p_h, *p_gat, *p_h1, *p_h2;
    cudaGetSymbolAddress(&p_h,   g_h);
    cudaGetSymbolAddress(&p_gat, g_gat);
    cudaGetSymbolAddress(&p_h1,  g_h1);
    cudaGetSymbolAddress(&p_h2,  g_h2);

    int mBlocks = (n + 127) / 128;

    cudaFuncSetAttribute(k_mma<false, false, false>,
                         cudaFuncAttributeMaxDynamicSharedMemorySize, SMEM_BYTES);
    cudaFuncSetAttribute(k_mma<true, true, true>,
                         cudaFuncAttributeMaxDynamicSharedMemorySize, SMEM_BYTES);
    cudaFuncSetAttribute(k_mma<true, false, true>,
                         cudaFuncAttributeMaxDynamicSharedMemorySize, SMEM_BYTES);

    // CSR build + GEMM1 (ordered so the MMA GEMM lands in the ncu window)
    k_detect<<<1, 256>>>(ei, E);
    k_convert<<<2048, 256>>>(ei, E, n);
    k_zero<<<512, 256>>>(n);

    // h = x @ W
    k_mma<false, false, false><<<dim3(1, mBlocks), 256, SMEM_BYTES>>>(
        x, W, (float*)p_h, nullptr, nullptr, n, FDIM, FDIM);

    k_hist<<<2048, 256>>>(Etot);
    k_scan1<<<scanBlocks, SCAN_T>>>(n);
    k_scan2<<<1, 256>>>(scanBlocks);
    k_scan3<<<scanBlocks, SCAN_T>>>(n, Etot);
    k_slot<<<2048, 256>>>(Etot);

    k_att<<<(n + 7) / 8, 256>>>(att_src, att_dst, n);
    k_gather<<<(n + 7) / 8, 256>>>(n);

    k_mma<true, true, true><<<dim3(2, mBlocks), 256, SMEM_BYTES>>>(
        (const float*)p_gat, W1, (float*)p_h1, bias, b1, n, HDIM, FDIM);
    k_mma<true, false, true><<<dim3(2, mBlocks), 256, SMEM_BYTES>>>(
        (const float*)p_h1, W2, (float*)p_h2, nullptr, b2, n, HDIM, HDIM);
    k_final<<<(n + 7) / 8, 256>>>(W3, b3, out, n);
}